// round 3
// baseline (speedup 1.0000x reference)
#include <cuda_runtime.h>
#include <math.h>

#define BATCH 4
#define CH 64
#define HW 64
#define LL 1024        // 32*32 kernel patches
#define PP 3969        // 63*63 f patches
#define KD 1024        // C * 4 * 4
#define HS 63

static const int TOT = BATCH * LL * PP;   // 16,257,024

// ---------------- scratch (static device arrays; no allocation) -------------
__device__ float g_F  [(size_t)BATCH * PP * KD];   // f patch matrix, reused as c1 after GEMM
__device__ float g_Km [(size_t)BATCH * LL * KD];   // normalized b patch kernels
__device__ float g_cos[(size_t)BATCH * LL * PP];   // GEMM output
__device__ float g_rnorm[BATCH * CH];
__device__ float g_mmk[BATCH * LL];
__device__ float g_mmp[BATCH * PP];

__device__ __forceinline__ int clamp64(int v) { return min(max(v, 0), 63); }

// ---------------- per-(b,c) inverse L2 norm of b ----------------------------
__global__ void norm_kernel(const float* __restrict__ bin) {
    int bc = blockIdx.x;                       // 0..255
    const float* ptr = bin + (size_t)bc * 4096;
    float s = 0.f;
    for (int i = threadIdx.x; i < 4096; i += 256) { float v = ptr[i]; s += v * v; }
    __shared__ float red[256];
    red[threadIdx.x] = s; __syncthreads();
    for (int st = 128; st > 0; st >>= 1) {
        if (threadIdx.x < st) red[threadIdx.x] += red[threadIdx.x + st];
        __syncthreads();
    }
    if (threadIdx.x == 0) g_rnorm[bc] = 1.0f / sqrtf(red[0] + 1e-8f);
}

// ---------------- build kernel matrix Km[b][l][k], k = c*16+i*4+j -----------
__global__ void buildK(const float* __restrict__ bin) {
    int idx = blockIdx.x * blockDim.x + threadIdx.x;
    if (idx >= BATCH * LL * CH * 4) return;
    int i = idx & 3;
    int c = (idx >> 2) & 63;
    int l = (idx >> 8) & 1023;
    int b = idx >> 18;
    int gy = l >> 5, gx = l & 31;
    int row = clamp64(gy * 2 + i - 1);
    float rn = g_rnorm[b * 64 + c];
    const float* src = bin + (((size_t)b * 64 + c) * 64 + row) * 64;
    int x0 = gx * 2 - 1;
    float4 v;
    v.x = src[clamp64(x0 + 0)] * rn;
    v.y = src[clamp64(x0 + 1)] * rn;
    v.z = src[clamp64(x0 + 2)] * rn;
    v.w = src[clamp64(x0 + 3)] * rn;
    *(float4*)&g_Km[(size_t)idx * 4] = v;
}

// ---------------- build f patch matrix F[b][p][k] ---------------------------
__global__ void buildF(const float* __restrict__ fin) {
    int idx = blockIdx.x * blockDim.x + threadIdx.x;
    if (idx >= BATCH * PP * CH * 4) return;
    int i = idx & 3;
    int c = (idx >> 2) & 63;
    int rem = idx >> 8;
    int p = rem % PP;
    int b = rem / PP;
    int y = p / 63, x = p % 63;
    int row = clamp64(y + i - 1);
    const float* src = fin + (((size_t)b * 64 + c) * 64 + row) * 64;
    int x0 = x - 1;
    float4 v;
    v.x = src[clamp64(x0 + 0)];
    v.y = src[clamp64(x0 + 1)];
    v.z = src[clamp64(x0 + 2)];
    v.w = src[clamp64(x0 + 3)];
    *(float4*)&g_F[(size_t)idx * 4] = v;
}

// ---------------- mask patch means ------------------------------------------
__global__ void mmk_kernel(const float* __restrict__ mask) {
    int idx = blockIdx.x * blockDim.x + threadIdx.x;
    if (idx >= BATCH * LL) return;
    int b = idx >> 10, l = idx & 1023;
    int gy = l >> 5, gx = l & 31;
    const float* mp = mask + (size_t)b * 4096;
    float s = 0.f;
    #pragma unroll
    for (int i = 0; i < 4; i++) {
        int r = clamp64(gy * 2 + i - 1);
        #pragma unroll
        for (int j = 0; j < 4; j++)
            s += 1.0f - mp[r * 64 + clamp64(gx * 2 + j - 1)];
    }
    g_mmk[idx] = s * 0.0625f;
}

__global__ void mmp_kernel(const float* __restrict__ mask) {
    int idx = blockIdx.x * blockDim.x + threadIdx.x;
    if (idx >= BATCH * PP) return;
    int b = idx / PP, p = idx % PP;
    int y = p / 63, x = p % 63;
    const float* mp = mask + (size_t)b * 4096;
    float s = 0.f;
    #pragma unroll
    for (int i = 0; i < 4; i++) {
        int r = clamp64(y + i - 1);
        #pragma unroll
        for (int j = 0; j < 4; j++)
            s += 1.0f - mp[r * 64 + clamp64(x + j - 1)];
    }
    g_mmp[idx] = s * 0.0625f;
}

// ---------------- SGEMM: cos[l][p] = sum_k Km[l][k] * F[p][k] ----------------
// per batch: M=1024 (l), N=3969 (p), K=1024. Both operands K-major (NT GEMM).
__global__ __launch_bounds__(256, 2) void sgemm_kernel() {
    const int M = LL, N = PP, K = KD;
    int bz = blockIdx.z;
    const float* A = g_Km + (size_t)bz * M * K;
    const float* B = g_F  + (size_t)bz * N * K;
    float*       C = g_cos + (size_t)bz * M * N;

    int bm = blockIdx.y * 128;
    int bn = blockIdx.x * 128;

    __shared__ float As[16][132];
    __shared__ float Bs[16][132];

    int t = threadIdx.x;
    int tm = t >> 4, tn = t & 15;
    int lr0 = t >> 2;            // 0..63
    int lk4 = (t & 3) * 4;       // 0,4,8,12

    float acc[8][8];
    #pragma unroll
    for (int i = 0; i < 8; i++)
        #pragma unroll
        for (int j = 0; j < 8; j++) acc[i][j] = 0.f;

    for (int k0 = 0; k0 < K; k0 += 16) {
        #pragma unroll
        for (int h = 0; h < 2; h++) {
            int r = lr0 + h * 64;
            float4 va = *(const float4*)(A + (size_t)(bm + r) * K + k0 + lk4);
            As[lk4 + 0][r] = va.x; As[lk4 + 1][r] = va.y;
            As[lk4 + 2][r] = va.z; As[lk4 + 3][r] = va.w;
            int rn = bn + r;
            float4 vb;
            if (rn < N) vb = *(const float4*)(B + (size_t)rn * K + k0 + lk4);
            else        vb = make_float4(0.f, 0.f, 0.f, 0.f);
            Bs[lk4 + 0][r] = vb.x; Bs[lk4 + 1][r] = vb.y;
            Bs[lk4 + 2][r] = vb.z; Bs[lk4 + 3][r] = vb.w;
        }
        __syncthreads();
        #pragma unroll
        for (int kk = 0; kk < 16; kk++) {
            float4 a0 = *(const float4*)&As[kk][tm * 8];
            float4 a1 = *(const float4*)&As[kk][tm * 8 + 4];
            float4 b0 = *(const float4*)&Bs[kk][tn * 8];
            float4 b1 = *(const float4*)&Bs[kk][tn * 8 + 4];
            float a[8] = {a0.x, a0.y, a0.z, a0.w, a1.x, a1.y, a1.z, a1.w};
            float bb[8] = {b0.x, b0.y, b0.z, b0.w, b1.x, b1.y, b1.z, b1.w};
            #pragma unroll
            for (int i = 0; i < 8; i++)
                #pragma unroll
                for (int j = 0; j < 8; j++)
                    acc[i][j] = fmaf(a[i], bb[j], acc[i][j]);
        }
        __syncthreads();
    }

    #pragma unroll
    for (int i = 0; i < 8; i++) {
        float* crow = C + (size_t)(bm + tm * 8 + i) * N + bn + tn * 8;
        #pragma unroll
        for (int j = 0; j < 8; j++)
            if (bn + tn * 8 + j < N) crow[j] = acc[i][j];
    }
}

// ---------------- diag3 pass 1 on flattened (l, s) grid ---------------------
__global__ void pass1_kernel() {
    int idx = blockIdx.x * blockDim.x + threadIdx.x;
    if (idx >= TOT) return;
    int ls = idx % (LL * PP);
    int l = ls / PP, s = ls % PP;
    float v = g_cos[idx];
    if (l > 0    && s > 0)      v += g_cos[idx - PP - 1];
    if (l < 1023 && s < PP - 1) v += g_cos[idx + PP + 1];
    g_F[idx] = v;    // reuse g_F as c1 buffer
}

// ---------------- diag3 pass 2 (transposed spaces) + mask + scale -----------
__global__ void pass2_kernel(float* __restrict__ out) {
    int idx = blockIdx.x * blockDim.x + threadIdx.x;
    if (idx >= TOT) return;
    int b  = idx / (LL * PP);
    int ls = idx % (LL * PP);
    int l = ls / PP, s = ls % PP;
    int y = s / 63, x = s % 63;
    int lh = l >> 5, lw = l & 31;
    int lp = lw * 32 + lh;
    int sp = x * 63 + y;
    const float* c1 = g_F + (size_t)b * LL * PP;
    float v = 0.f;
    #pragma unroll
    for (int d = -1; d <= 1; d++) {
        int a = lp + d, tt = sp + d;
        if (a >= 0 && a < LL && tt >= 0 && tt < PP) {
            int l2 = ((a & 31) << 5) + (a >> 5);
            int s2 = (tt % 63) * 63 + (tt / 63);
            v += c1[(size_t)l2 * PP + s2];
        }
    }
    float mk = g_mmk[b * LL + l];
    float mp = g_mmp[b * PP + s];
    bool mm = ((mk > mp) && (mp > 0.5f)) || (mk == 1.0f);
    out[idx] = mm ? v * 10.0f : 0.0f;
}

// ---------------- softmax over l (stride PP) --------------------------------
__global__ void softmax_kernel(float* __restrict__ out) {
    int y = blockIdx.x;           // 0..62
    int b = blockIdx.y;           // 0..3
    int tx = threadIdx.x & 63;    // x lane (active if < 63)
    int tj = threadIdx.x >> 6;    // 0..3
    __shared__ float sm[4][64];
    __shared__ float ss[4][64];
    const size_t base = (size_t)b * LL * PP + (size_t)y * 63 + tx;
    float m = -1e30f, s = 0.f;
    if (tx < 63) {
        for (int l = tj; l < LL; l += 4) {
            float v = out[base + (size_t)l * PP];
            float nm = fmaxf(m, v);
            s = s * __expf(m - nm) + __expf(v - nm);
            m = nm;
        }
    }
    sm[tj][tx] = m; ss[tj][tx] = s;
    __syncthreads();
    if (tj == 0 && tx < 63) {
        float M = sm[0][tx], S = ss[0][tx];
        #pragma unroll
        for (int k = 1; k < 4; k++) {
            float m2 = sm[k][tx], s2 = ss[k][tx];
            float nm = fmaxf(M, m2);
            S = S * __expf(M - nm) + s2 * __expf(m2 - nm);
            M = nm;
        }
        sm[0][tx] = M; ss[0][tx] = 1.0f / S;
    }
    __syncthreads();
    if (tx < 63) {
        float M = sm[0][tx], R = ss[0][tx];
        for (int l = tj; l < LL; l += 4) {
            size_t o = base + (size_t)l * PP;
            out[o] = __expf(out[o] - M) * R;
        }
    }
}

// ---------------- launch ----------------------------------------------------
extern "C" void kernel_launch(void* const* d_in, const int* in_sizes, int n_in,
                              void* d_out, int out_size) {
    const float* f    = (const float*)d_in[0];
    const float* b    = (const float*)d_in[1];
    const float* mask = (const float*)d_in[2];
    float* out = (float*)d_out;

    norm_kernel<<<BATCH * CH, 256>>>(b);
    buildK<<<(BATCH * LL * CH * 4 + 255) / 256, 256>>>(b);
    buildF<<<(BATCH * PP * CH * 4 + 255) / 256, 256>>>(f);
    mmk_kernel<<<(BATCH * LL + 255) / 256, 256>>>(mask);
    mmp_kernel<<<(BATCH * PP + 255) / 256, 256>>>(mask);

    sgemm_kernel<<<dim3(32, 8, BATCH), 256>>>();

    int nb = (TOT + 255) / 256;
    pass1_kernel<<<nb, 256>>>();
    pass2_kernel<<<nb, 256>>>(out);
    softmax_kernel<<<dim3(63, BATCH), 256>>>(out);
}

// round 6
// speedup vs baseline: 1.6832x; 1.6832x over previous
#include <cuda_runtime.h>
#include <cuda_bf16.h>
#include <math.h>
#include <stdint.h>

#define BATCH 4
#define CH 64
#define LL 1024        // 32*32 kernel patches
#define PP 3969        // 63*63 f patches
#define PPpad 4096
#define KD 1024        // C * 4 * 4
#define BK 32          // K halves per chunk
#define NCHUNK (KD / BK)   // 32
#define NSTAGE 4

static const int TOT = BATCH * LL * PP;

// ---------------- scratch (static device arrays; no allocation) -------------
__device__ __nv_bfloat16 g_Kh[(size_t)BATCH * LL * KD];
__device__ __nv_bfloat16 g_Kl[(size_t)BATCH * LL * KD];
__device__ __nv_bfloat16 g_Fh[(size_t)BATCH * PPpad * KD];
__device__ __nv_bfloat16 g_Fl[(size_t)BATCH * PPpad * KD];
__device__ float g_cos[(size_t)BATCH * LL * PP];
__device__ float g_c1 [(size_t)BATCH * LL * PP];
__device__ float g_rnorm[BATCH * CH];
__device__ float g_mmk[BATCH * LL];
__device__ float g_mmp[BATCH * PP];

__device__ __forceinline__ int clamp64(int v) { return min(max(v, 0), 63); }

// ---------------- PTX helpers (baseline ISA only — no sm_103a features) -----
__device__ __forceinline__ uint32_t smem_u32(const void* p) {
    uint32_t a;
    asm("{ .reg .u64 t; cvta.to.shared.u64 t, %1; cvt.u32.u64 %0, t; }" : "=r"(a) : "l"(p));
    return a;
}
#define CP_ASYNC16(dst, src) \
    asm volatile("cp.async.cg.shared.global [%0], [%1], 16;" :: "r"(dst), "l"(src) : "memory")
#define CP_COMMIT() asm volatile("cp.async.commit_group;" ::: "memory")
#define CP_WAIT2()  asm volatile("cp.async.wait_group 2;" ::: "memory")

#define LDSM_X4(r0, r1, r2, r3, addr) \
    asm volatile("ldmatrix.sync.aligned.m8n8.x4.shared.b16 {%0,%1,%2,%3}, [%4];" \
        : "=r"(r0), "=r"(r1), "=r"(r2), "=r"(r3) : "r"(addr))

#define HMMA(d, a, b) \
    asm volatile("mma.sync.aligned.m16n8k16.row.col.f32.bf16.bf16.f32 " \
        "{%0,%1,%2,%3}, {%4,%5,%6,%7}, {%8,%9}, {%0,%1,%2,%3};" \
        : "+f"((d)[0]), "+f"((d)[1]), "+f"((d)[2]), "+f"((d)[3]) \
        : "r"((a)[0]), "r"((a)[1]), "r"((a)[2]), "r"((a)[3]), \
          "r"((b)[0]), "r"((b)[1]))

__device__ __forceinline__ uint32_t pack_bf2(float a, float b) {
    __nv_bfloat162 t = __floats2bfloat162_rn(a, b);
    return *(uint32_t*)&t;
}

// ---------------- per-(b,c) inverse L2 norm of b ----------------------------
__global__ void norm_kernel(const float* __restrict__ bin) {
    int bc = blockIdx.x;
    const float* ptr = bin + (size_t)bc * 4096;
    float s = 0.f;
    for (int i = threadIdx.x; i < 4096; i += 256) { float v = ptr[i]; s += v * v; }
    __shared__ float red[256];
    red[threadIdx.x] = s; __syncthreads();
    for (int st = 128; st > 0; st >>= 1) {
        if (threadIdx.x < st) red[threadIdx.x] += red[threadIdx.x + st];
        __syncthreads();
    }
    if (threadIdx.x == 0) g_rnorm[bc] = 1.0f / sqrtf(red[0] + 1e-8f);
}

// ---------------- build kernel matrix (bf16 hi/lo), k = c*16+i*4+j ----------
__global__ void buildK(const float* __restrict__ bin) {
    int idx = blockIdx.x * blockDim.x + threadIdx.x;
    if (idx >= BATCH * LL * CH * 4) return;
    int i = idx & 3;
    int c = (idx >> 2) & 63;
    int l = (idx >> 8) & 1023;
    int b = idx >> 18;
    int gy = l >> 5, gx = l & 31;
    int row = clamp64(gy * 2 + i - 1);
    float rn = g_rnorm[b * 64 + c];
    const float* src = bin + (((size_t)b * 64 + c) * 64 + row) * 64;
    int x0 = gx * 2 - 1;
    float v[4];
    v[0] = src[clamp64(x0 + 0)] * rn;
    v[1] = src[clamp64(x0 + 1)] * rn;
    v[2] = src[clamp64(x0 + 2)] * rn;
    v[3] = src[clamp64(x0 + 3)] * rn;
    float h[4], lo[4];
    #pragma unroll
    for (int j = 0; j < 4; j++) {
        h[j] = __bfloat162float(__float2bfloat16_rn(v[j]));
        lo[j] = v[j] - h[j];
    }
    uint2 hh = make_uint2(pack_bf2(h[0], h[1]), pack_bf2(h[2], h[3]));
    uint2 ll = make_uint2(pack_bf2(lo[0], lo[1]), pack_bf2(lo[2], lo[3]));
    *(uint2*)&g_Kh[(size_t)idx * 4] = hh;
    *(uint2*)&g_Kl[(size_t)idx * 4] = ll;
}

// ---------------- build f patch matrix (bf16 hi/lo), padded to 4096 rows ----
__global__ void buildF(const float* __restrict__ fin) {
    int idx = blockIdx.x * blockDim.x + threadIdx.x;
    if (idx >= BATCH * PPpad * CH * 4) return;
    int i = idx & 3;
    int c = (idx >> 2) & 63;
    int rem = idx >> 8;
    int p = rem & (PPpad - 1);
    int b = rem >> 12;
    if (p >= PP) p = PP - 1;           // duplicate pad rows (never stored to C)
    int y = p / 63, x = p % 63;
    int row = clamp64(y + i - 1);
    const float* src = fin + (((size_t)b * 64 + c) * 64 + row) * 64;
    int x0 = x - 1;
    float v[4];
    v[0] = src[clamp64(x0 + 0)];
    v[1] = src[clamp64(x0 + 1)];
    v[2] = src[clamp64(x0 + 2)];
    v[3] = src[clamp64(x0 + 3)];
    float h[4], lo[4];
    #pragma unroll
    for (int j = 0; j < 4; j++) {
        h[j] = __bfloat162float(__float2bfloat16_rn(v[j]));
        lo[j] = v[j] - h[j];
    }
    uint2 hh = make_uint2(pack_bf2(h[0], h[1]), pack_bf2(h[2], h[3]));
    uint2 ll = make_uint2(pack_bf2(lo[0], lo[1]), pack_bf2(lo[2], lo[3]));
    *(uint2*)&g_Fh[(size_t)idx * 4] = hh;
    *(uint2*)&g_Fl[(size_t)idx * 4] = ll;
}

// ---------------- mask patch means ------------------------------------------
__global__ void mmk_kernel(const float* __restrict__ mask) {
    int idx = blockIdx.x * blockDim.x + threadIdx.x;
    if (idx >= BATCH * LL) return;
    int b = idx >> 10, l = idx & 1023;
    int gy = l >> 5, gx = l & 31;
    const float* mp = mask + (size_t)b * 4096;
    float s = 0.f;
    #pragma unroll
    for (int i = 0; i < 4; i++) {
        int r = clamp64(gy * 2 + i - 1);
        #pragma unroll
        for (int j = 0; j < 4; j++)
            s += 1.0f - mp[r * 64 + clamp64(gx * 2 + j - 1)];
    }
    g_mmk[idx] = s * 0.0625f;
}

__global__ void mmp_kernel(const float* __restrict__ mask) {
    int idx = blockIdx.x * blockDim.x + threadIdx.x;
    if (idx >= BATCH * PP) return;
    int b = idx / PP, p = idx % PP;
    int y = p / 63, x = p % 63;
    const float* mp = mask + (size_t)b * 4096;
    float s = 0.f;
    #pragma unroll
    for (int i = 0; i < 4; i++) {
        int r = clamp64(y + i - 1);
        #pragma unroll
        for (int j = 0; j < 4; j++)
            s += 1.0f - mp[r * 64 + clamp64(x + j - 1)];
    }
    g_mmp[idx] = s * 0.0625f;
}

// ---------------- warp-MMA GEMM: cos = Km · F^T (bf16 3-split) --------------
// Stage layout (per 128x32-half tiles, 80B row stride for conflict-free LDSM):
//   Ah @0, Al @10240, Bh @20480, Bl @30720 ; stage = 40960 B, 4 stages.
#define OFF_AH 0
#define OFF_AL 10240
#define OFF_BH 20480
#define OFF_BL 30720
#define STAGE_BYTES 40960
#define SMEM_GEMM_TOTAL (NSTAGE * STAGE_BYTES)   // 163840

__global__ __launch_bounds__(256, 1) void gemm_mma_kernel() {
    extern __shared__ char smem[];
    const uint32_t sb = smem_u32(smem);
    const int tid = threadIdx.x;
    const int wid = tid >> 5;
    const int lane = tid & 31;

    const int bz = blockIdx.z;
    const int bm = blockIdx.y * 128;
    const int bn = blockIdx.x * 128;

    const __nv_bfloat16* Ah = g_Kh + (size_t)bz * LL * KD;
    const __nv_bfloat16* Al = g_Kl + (size_t)bz * LL * KD;
    const __nv_bfloat16* Bh = g_Fh + (size_t)bz * PPpad * KD;
    const __nv_bfloat16* Bl = g_Fl + (size_t)bz * PPpad * KD;
    float* C = g_cos + (size_t)bz * LL * PP;

    // ---- load mapping: thread t -> row t/2, units (t&1)*2, +1 ----
    const int lrow = tid >> 1;
    const int lu0 = (tid & 1) * 2;
    const size_t a_off = (size_t)(bm + lrow) * KD + lu0 * 8;
    const size_t b_off = (size_t)(bn + lrow) * KD + lu0 * 8;
    const uint32_t s_dst = (uint32_t)(lrow * 80 + lu0 * 16);

    // ---- warp tile ----
    const int wm = (wid >> 2) * 64;
    const int wn = (wid & 3) * 32;

    // ldmatrix source rows/units per lane
    const int lm_r = lane & 7;
    const int lm_mi = lane >> 3;            // 0..3
    // A: row += (mi&1)*8 ; unit += mi>>1
    const int a_rowadd = (lm_mi & 1) * 8;
    const int a_uadd = lm_mi >> 1;
    // B: row += (mi>>1)*8 ; unit += mi&1
    const int b_rowadd = (lm_mi >> 1) * 8;
    const int b_uadd = lm_mi & 1;

    float acc[4][4][4];
    #pragma unroll
    for (int i = 0; i < 4; i++)
        #pragma unroll
        for (int j = 0; j < 4; j++)
            #pragma unroll
            for (int q = 0; q < 4; q++) acc[i][j][q] = 0.f;

    // ---- prologue: preload NSTAGE-1 chunks ----
    #pragma unroll
    for (int c = 0; c < NSTAGE - 1; c++) {
        const uint32_t st = sb + (uint32_t)(c % NSTAGE) * STAGE_BYTES;
        const size_t ka = (size_t)c * BK;
        CP_ASYNC16(st + OFF_AH + s_dst,      Ah + a_off + ka);
        CP_ASYNC16(st + OFF_AH + s_dst + 16, Ah + a_off + ka + 8);
        CP_ASYNC16(st + OFF_AL + s_dst,      Al + a_off + ka);
        CP_ASYNC16(st + OFF_AL + s_dst + 16, Al + a_off + ka + 8);
        CP_ASYNC16(st + OFF_BH + s_dst,      Bh + b_off + ka);
        CP_ASYNC16(st + OFF_BH + s_dst + 16, Bh + b_off + ka + 8);
        CP_ASYNC16(st + OFF_BL + s_dst,      Bl + b_off + ka);
        CP_ASYNC16(st + OFF_BL + s_dst + 16, Bl + b_off + ka + 8);
        CP_COMMIT();
    }

    for (int c = 0; c < NCHUNK; c++) {
        CP_WAIT2();
        __syncthreads();
        const uint32_t st = sb + (uint32_t)(c % NSTAGE) * STAGE_BYTES;

        #pragma unroll
        for (int kstep = 0; kstep < 2; kstep++) {
            uint32_t aH[4][4], aL[4][4];
            #pragma unroll
            for (int mt = 0; mt < 4; mt++) {
                int row = wm + mt * 16 + lm_r + a_rowadd;
                int unit = kstep * 2 + a_uadd;
                uint32_t ad = st + OFF_AH + row * 80 + unit * 16;
                LDSM_X4(aH[mt][0], aH[mt][1], aH[mt][2], aH[mt][3], ad);
                LDSM_X4(aL[mt][0], aL[mt][1], aL[mt][2], aL[mt][3],
                        ad + (OFF_AL - OFF_AH));
            }
            uint32_t bH[4][2], bL[4][2];
            #pragma unroll
            for (int bt = 0; bt < 2; bt++) {
                int row = wn + bt * 16 + lm_r + b_rowadd;
                int unit = kstep * 2 + b_uadd;
                uint32_t ad = st + OFF_BH + row * 80 + unit * 16;
                LDSM_X4(bH[2 * bt][0], bH[2 * bt][1],
                        bH[2 * bt + 1][0], bH[2 * bt + 1][1], ad);
                LDSM_X4(bL[2 * bt][0], bL[2 * bt][1],
                        bL[2 * bt + 1][0], bL[2 * bt + 1][1],
                        ad + (OFF_BL - OFF_BH));
            }
            #pragma unroll
            for (int mt = 0; mt < 4; mt++)
                #pragma unroll
                for (int nt = 0; nt < 4; nt++) {
                    HMMA(acc[mt][nt], aH[mt], bH[nt]);
                    HMMA(acc[mt][nt], aH[mt], bL[nt]);
                    HMMA(acc[mt][nt], aL[mt], bH[nt]);
                }
        }

        const int cn = c + NSTAGE - 1;
        if (cn < NCHUNK) {
            const uint32_t sn = sb + (uint32_t)(cn % NSTAGE) * STAGE_BYTES;
            const size_t ka = (size_t)cn * BK;
            CP_ASYNC16(sn + OFF_AH + s_dst,      Ah + a_off + ka);
            CP_ASYNC16(sn + OFF_AH + s_dst + 16, Ah + a_off + ka + 8);
            CP_ASYNC16(sn + OFF_AL + s_dst,      Al + a_off + ka);
            CP_ASYNC16(sn + OFF_AL + s_dst + 16, Al + a_off + ka + 8);
            CP_ASYNC16(sn + OFF_BH + s_dst,      Bh + b_off + ka);
            CP_ASYNC16(sn + OFF_BH + s_dst + 16, Bh + b_off + ka + 8);
            CP_ASYNC16(sn + OFF_BL + s_dst,      Bl + b_off + ka);
            CP_ASYNC16(sn + OFF_BL + s_dst + 16, Bl + b_off + ka + 8);
        }
        CP_COMMIT();
    }

    // ---- epilogue: direct stores (row gm, cols gn, gn+1) ----
    const int er = lane >> 2;
    const int ec = (lane & 3) * 2;
    #pragma unroll
    for (int mt = 0; mt < 4; mt++) {
        #pragma unroll
        for (int nt = 0; nt < 4; nt++) {
            int gn = bn + wn + nt * 8 + ec;
            if (gn >= PP) continue;
            int gm0 = bm + wm + mt * 16 + er;
            float* p0 = C + (size_t)gm0 * PP + gn;
            float* p1 = C + (size_t)(gm0 + 8) * PP + gn;
            p0[0] = acc[mt][nt][0];
            p1[0] = acc[mt][nt][2];
            if (gn + 1 < PP) {
                p0[1] = acc[mt][nt][1];
                p1[1] = acc[mt][nt][3];
            }
        }
    }
}

// ---------------- diag3 pass 1 on flattened (l, s) grid ---------------------
__global__ void pass1_kernel() {
    int idx = blockIdx.x * blockDim.x + threadIdx.x;
    if (idx >= TOT) return;
    int ls = idx % (LL * PP);
    int l = ls / PP, s = ls % PP;
    float v = g_cos[idx];
    if (l > 0    && s > 0)      v += g_cos[idx - PP - 1];
    if (l < 1023 && s < PP - 1) v += g_cos[idx + PP + 1];
    g_c1[idx] = v;
}

// ---------------- diag3 pass 2 (transposed spaces) + mask + scale -----------
__global__ void pass2_kernel(float* __restrict__ out) {
    int idx = blockIdx.x * blockDim.x + threadIdx.x;
    if (idx >= TOT) return;
    int b  = idx / (LL * PP);
    int ls = idx % (LL * PP);
    int l = ls / PP, s = ls % PP;
    int y = s / 63, x = s % 63;
    int lh = l >> 5, lw = l & 31;
    int lp = lw * 32 + lh;
    int sp = x * 63 + y;
    const float* c1 = g_c1 + (size_t)b * LL * PP;
    float v = 0.f;
    #pragma unroll
    for (int d = -1; d <= 1; d++) {
        int a = lp + d, tt = sp + d;
        if (a >= 0 && a < LL && tt >= 0 && tt < PP) {
            int l2 = ((a & 31) << 5) + (a >> 5);
            int s2 = (tt % 63) * 63 + (tt / 63);
            v += c1[(size_t)l2 * PP + s2];
        }
    }
    float mk = g_mmk[b * LL + l];
    float mp = g_mmp[b * PP + s];
    bool mm = ((mk > mp) && (mp > 0.5f)) || (mk == 1.0f);
    out[idx] = mm ? v * 10.0f : 0.0f;
}

// ---------------- softmax over l (stride PP) --------------------------------
__global__ void softmax_kernel(float* __restrict__ out) {
    int y = blockIdx.x;
    int b = blockIdx.y;
    int tx = threadIdx.x & 63;
    int tj = threadIdx.x >> 6;
    __shared__ float sm[4][64];
    __shared__ float ss[4][64];
    const size_t base = (size_t)b * LL * PP + (size_t)y * 63 + tx;
    float m = -1e30f, s = 0.f;
    if (tx < 63) {
        for (int l = tj; l < LL; l += 4) {
            float v = out[base + (size_t)l * PP];
            float nm = fmaxf(m, v);
            s = s * __expf(m - nm) + __expf(v - nm);
            m = nm;
        }
    }
    sm[tj][tx] = m; ss[tj][tx] = s;
    __syncthreads();
    if (tj == 0 && tx < 63) {
        float M = sm[0][tx], S = ss[0][tx];
        #pragma unroll
        for (int k = 1; k < 4; k++) {
            float m2 = sm[k][tx], s2 = ss[k][tx];
            float nm = fmaxf(M, m2);
            S = S * __expf(M - nm) + s2 * __expf(m2 - nm);
            M = nm;
        }
        sm[0][tx] = M; ss[0][tx] = 1.0f / S;
    }
    __syncthreads();
    if (tx < 63) {
        float M = sm[0][tx], R = ss[0][tx];
        for (int l = tj; l < LL; l += 4) {
            size_t o = base + (size_t)l * PP;
            out[o] = __expf(out[o] - M) * R;
        }
    }
}

// ---------------- launch ----------------------------------------------------
extern "C" void kernel_launch(void* const* d_in, const int* in_sizes, int n_in,
                              void* d_out, int out_size) {
    const float* f    = (const float*)d_in[0];
    const float* b    = (const float*)d_in[1];
    const float* mask = (const float*)d_in[2];
    float* out = (float*)d_out;

    cudaFuncSetAttribute(gemm_mma_kernel,
                         cudaFuncAttributeMaxDynamicSharedMemorySize, SMEM_GEMM_TOTAL);

    norm_kernel<<<BATCH * CH, 256>>>(b);
    buildK<<<(BATCH * LL * CH * 4 + 255) / 256, 256>>>(b);
    buildF<<<(BATCH * PPpad * CH * 4 + 255) / 256, 256>>>(f);
    mmk_kernel<<<(BATCH * LL + 255) / 256, 256>>>(mask);
    mmp_kernel<<<(BATCH * PP + 255) / 256, 256>>>(mask);

    gemm_mma_kernel<<<dim3(PPpad / 128, LL / 128, BATCH), 256, SMEM_GEMM_TOTAL>>>();

    int nb = (TOT + 255) / 256;
    pass1_kernel<<<nb, 256>>>();
    pass2_kernel<<<nb, 256>>>(out);
    softmax_kernel<<<dim3(63, BATCH), 256>>>(out);
}

// round 7
// speedup vs baseline: 1.7574x; 1.0440x over previous
#include <cuda_runtime.h>
#include <cuda_bf16.h>
#include <math.h>
#include <stdint.h>

#define BATCH 4
#define CH 64
#define LL 1024        // 32*32 kernel patches
#define PP 3969        // 63*63 f patches
#define PPpad 4096
#define KD 1024        // C * 4 * 4
#define BK 32          // K halves per chunk
#define NCHUNK (KD / BK)   // 32
#define NSTAGE 2

static const int TOT = BATCH * LL * PP;

// ---------------- scratch (static device arrays; no allocation) -------------
__device__ __nv_bfloat16 g_Kh[(size_t)BATCH * LL * KD];
__device__ __nv_bfloat16 g_Kl[(size_t)BATCH * LL * KD];
__device__ __nv_bfloat16 g_Fh[(size_t)BATCH * PPpad * KD];
__device__ __nv_bfloat16 g_Fl[(size_t)BATCH * PPpad * KD];
__device__ float g_cos[(size_t)BATCH * LL * PP];
__device__ float g_c1 [(size_t)BATCH * LL * PP];
__device__ float g_rnorm[BATCH * CH];
__device__ float g_mmk[BATCH * LL];
__device__ float g_mmp[BATCH * PP];

__device__ __forceinline__ int clamp64(int v) { return min(max(v, 0), 63); }

// ---------------- PTX helpers (baseline ISA only) ---------------------------
__device__ __forceinline__ uint32_t smem_u32(const void* p) {
    uint32_t a;
    asm("{ .reg .u64 t; cvta.to.shared.u64 t, %1; cvt.u32.u64 %0, t; }" : "=r"(a) : "l"(p));
    return a;
}
#define CP_ASYNC16(dst, src) \
    asm volatile("cp.async.cg.shared.global [%0], [%1], 16;" :: "r"(dst), "l"(src) : "memory")
#define CP_COMMIT() asm volatile("cp.async.commit_group;" ::: "memory")
#define CP_WAIT1()  asm volatile("cp.async.wait_group 1;" ::: "memory")
#define CP_WAIT0()  asm volatile("cp.async.wait_group 0;" ::: "memory")

#define LDSM_X4(r0, r1, r2, r3, addr) \
    asm volatile("ldmatrix.sync.aligned.m8n8.x4.shared.b16 {%0,%1,%2,%3}, [%4];" \
        : "=r"(r0), "=r"(r1), "=r"(r2), "=r"(r3) : "r"(addr))

#define HMMA(d, a, b) \
    asm volatile("mma.sync.aligned.m16n8k16.row.col.f32.bf16.bf16.f32 " \
        "{%0,%1,%2,%3}, {%4,%5,%6,%7}, {%8,%9}, {%0,%1,%2,%3};" \
        : "+f"((d)[0]), "+f"((d)[1]), "+f"((d)[2]), "+f"((d)[3]) \
        : "r"((a)[0]), "r"((a)[1]), "r"((a)[2]), "r"((a)[3]), \
          "r"((b)[0]), "r"((b)[1]))

__device__ __forceinline__ uint32_t pack_bf2(float a, float b) {
    __nv_bfloat162 t = __floats2bfloat162_rn(a, b);
    return *(uint32_t*)&t;
}

// ---------------- per-(b,c) inverse L2 norm of b ----------------------------
__global__ void norm_kernel(const float* __restrict__ bin) {
    int bc = blockIdx.x;
    const float* ptr = bin + (size_t)bc * 4096;
    float s = 0.f;
    for (int i = threadIdx.x; i < 4096; i += 256) { float v = ptr[i]; s += v * v; }
    __shared__ float red[256];
    red[threadIdx.x] = s; __syncthreads();
    for (int st = 128; st > 0; st >>= 1) {
        if (threadIdx.x < st) red[threadIdx.x] += red[threadIdx.x + st];
        __syncthreads();
    }
    if (threadIdx.x == 0) g_rnorm[bc] = 1.0f / sqrtf(red[0] + 1e-8f);
}

// ---------------- build kernel matrix (bf16 hi/lo), k = c*16+i*4+j ----------
__global__ void buildK(const float* __restrict__ bin) {
    int idx = blockIdx.x * blockDim.x + threadIdx.x;
    if (idx >= BATCH * LL * CH * 4) return;
    int i = idx & 3;
    int c = (idx >> 2) & 63;
    int l = (idx >> 8) & 1023;
    int b = idx >> 18;
    int gy = l >> 5, gx = l & 31;
    int row = clamp64(gy * 2 + i - 1);
    float rn = g_rnorm[b * 64 + c];
    const float* src = bin + (((size_t)b * 64 + c) * 64 + row) * 64;
    int x0 = gx * 2 - 1;
    float v[4];
    v[0] = src[clamp64(x0 + 0)] * rn;
    v[1] = src[clamp64(x0 + 1)] * rn;
    v[2] = src[clamp64(x0 + 2)] * rn;
    v[3] = src[clamp64(x0 + 3)] * rn;
    float h[4], lo[4];
    #pragma unroll
    for (int j = 0; j < 4; j++) {
        h[j] = __bfloat162float(__float2bfloat16_rn(v[j]));
        lo[j] = v[j] - h[j];
    }
    uint2 hh = make_uint2(pack_bf2(h[0], h[1]), pack_bf2(h[2], h[3]));
    uint2 ll = make_uint2(pack_bf2(lo[0], lo[1]), pack_bf2(lo[2], lo[3]));
    *(uint2*)&g_Kh[(size_t)idx * 4] = hh;
    *(uint2*)&g_Kl[(size_t)idx * 4] = ll;
}

// ---------------- build f patch matrix (bf16 hi/lo), padded to 4096 rows ----
__global__ void buildF(const float* __restrict__ fin) {
    int idx = blockIdx.x * blockDim.x + threadIdx.x;
    if (idx >= BATCH * PPpad * CH * 4) return;
    int i = idx & 3;
    int c = (idx >> 2) & 63;
    int rem = idx >> 8;
    int p = rem & (PPpad - 1);
    int b = rem >> 12;
    if (p >= PP) p = PP - 1;           // duplicate pad rows (never stored to C)
    int y = p / 63, x = p % 63;
    int row = clamp64(y + i - 1);
    const float* src = fin + (((size_t)b * 64 + c) * 64 + row) * 64;
    int x0 = x - 1;
    float v[4];
    v[0] = src[clamp64(x0 + 0)];
    v[1] = src[clamp64(x0 + 1)];
    v[2] = src[clamp64(x0 + 2)];
    v[3] = src[clamp64(x0 + 3)];
    float h[4], lo[4];
    #pragma unroll
    for (int j = 0; j < 4; j++) {
        h[j] = __bfloat162float(__float2bfloat16_rn(v[j]));
        lo[j] = v[j] - h[j];
    }
    uint2 hh = make_uint2(pack_bf2(h[0], h[1]), pack_bf2(h[2], h[3]));
    uint2 ll = make_uint2(pack_bf2(lo[0], lo[1]), pack_bf2(lo[2], lo[3]));
    *(uint2*)&g_Fh[(size_t)idx * 4] = hh;
    *(uint2*)&g_Fl[(size_t)idx * 4] = ll;
}

// ---------------- mask patch means ------------------------------------------
__global__ void mmk_kernel(const float* __restrict__ mask) {
    int idx = blockIdx.x * blockDim.x + threadIdx.x;
    if (idx >= BATCH * LL) return;
    int b = idx >> 10, l = idx & 1023;
    int gy = l >> 5, gx = l & 31;
    const float* mp = mask + (size_t)b * 4096;
    float s = 0.f;
    #pragma unroll
    for (int i = 0; i < 4; i++) {
        int r = clamp64(gy * 2 + i - 1);
        #pragma unroll
        for (int j = 0; j < 4; j++)
            s += 1.0f - mp[r * 64 + clamp64(gx * 2 + j - 1)];
    }
    g_mmk[idx] = s * 0.0625f;
}

__global__ void mmp_kernel(const float* __restrict__ mask) {
    int idx = blockIdx.x * blockDim.x + threadIdx.x;
    if (idx >= BATCH * PP) return;
    int b = idx / PP, p = idx % PP;
    int y = p / 63, x = p % 63;
    const float* mp = mask + (size_t)b * 4096;
    float s = 0.f;
    #pragma unroll
    for (int i = 0; i < 4; i++) {
        int r = clamp64(y + i - 1);
        #pragma unroll
        for (int j = 0; j < 4; j++)
            s += 1.0f - mp[r * 64 + clamp64(x + j - 1)];
    }
    g_mmp[idx] = s * 0.0625f;
}

// ---------------- warp-MMA GEMM: cos = Km · F^T (bf16 3-split) --------------
// Stage layout (128x32-half tiles, 80B row stride for conflict-free LDSM):
//   Ah @0, Al @10240, Bh @20480, Bl @30720 ; stage = 40960 B, 2 stages (80KB)
//   => 2 CTAs per SM.
#define OFF_AH 0
#define OFF_AL 10240
#define OFF_BH 20480
#define OFF_BL 30720
#define STAGE_BYTES 40960
#define SMEM_GEMM_TOTAL (NSTAGE * STAGE_BYTES)   // 81920

__global__ __launch_bounds__(256, 2) void gemm_mma_kernel() {
    extern __shared__ char smem[];
    const uint32_t sb = smem_u32(smem);
    const int tid = threadIdx.x;
    const int wid = tid >> 5;
    const int lane = tid & 31;

    const int bz = blockIdx.z;
    const int bm = blockIdx.y * 128;
    const int bn = blockIdx.x * 128;

    const __nv_bfloat16* Ah = g_Kh + (size_t)bz * LL * KD;
    const __nv_bfloat16* Al = g_Kl + (size_t)bz * LL * KD;
    const __nv_bfloat16* Bh = g_Fh + (size_t)bz * PPpad * KD;
    const __nv_bfloat16* Bl = g_Fl + (size_t)bz * PPpad * KD;
    float* C = g_cos + (size_t)bz * LL * PP;

    // ---- load mapping: thread t -> row t/2, units (t&1)*2, +1 ----
    const int lrow = tid >> 1;
    const int lu0 = (tid & 1) * 2;
    const size_t a_off = (size_t)(bm + lrow) * KD + lu0 * 8;
    const size_t b_off = (size_t)(bn + lrow) * KD + lu0 * 8;
    const uint32_t s_dst = (uint32_t)(lrow * 80 + lu0 * 16);

    // ---- warp tile: 2 (M) x 4 (N) warps, each 64x32 ----
    const int wm = (wid >> 2) * 64;
    const int wn = (wid & 3) * 32;

    const int lm_r = lane & 7;
    const int lm_mi = lane >> 3;            // 0..3
    const int a_rowadd = (lm_mi & 1) * 8;
    const int a_uadd = lm_mi >> 1;
    const int b_rowadd = (lm_mi >> 1) * 8;
    const int b_uadd = lm_mi & 1;

    float acc[4][4][4];
    #pragma unroll
    for (int i = 0; i < 4; i++)
        #pragma unroll
        for (int j = 0; j < 4; j++)
            #pragma unroll
            for (int q = 0; q < 4; q++) acc[i][j][q] = 0.f;

    // ---- prologue: preload stages 0,1 ----
    #pragma unroll
    for (int c = 0; c < NSTAGE; c++) {
        const uint32_t st = sb + (uint32_t)c * STAGE_BYTES;
        const size_t ka = (size_t)c * BK;
        CP_ASYNC16(st + OFF_AH + s_dst,      Ah + a_off + ka);
        CP_ASYNC16(st + OFF_AH + s_dst + 16, Ah + a_off + ka + 8);
        CP_ASYNC16(st + OFF_AL + s_dst,      Al + a_off + ka);
        CP_ASYNC16(st + OFF_AL + s_dst + 16, Al + a_off + ka + 8);
        CP_ASYNC16(st + OFF_BH + s_dst,      Bh + b_off + ka);
        CP_ASYNC16(st + OFF_BH + s_dst + 16, Bh + b_off + ka + 8);
        CP_ASYNC16(st + OFF_BL + s_dst,      Bl + b_off + ka);
        CP_ASYNC16(st + OFF_BL + s_dst + 16, Bl + b_off + ka + 8);
        CP_COMMIT();
    }

    for (int c = 0; c < NCHUNK; c++) {
        // stage c ready when at most one (the c+1 prefetch) group remains
        if (c < NCHUNK - 1) { CP_WAIT1(); } else { CP_WAIT0(); }
        __syncthreads();
        const uint32_t st = sb + (uint32_t)(c & 1) * STAGE_BYTES;

        #pragma unroll
        for (int kstep = 0; kstep < 2; kstep++) {
            uint32_t bHf[4][2], bLf[4][2];
            #pragma unroll
            for (int bt = 0; bt < 2; bt++) {
                int row = wn + bt * 16 + lm_r + b_rowadd;
                int unit = kstep * 2 + b_uadd;
                uint32_t ad = st + OFF_BH + row * 80 + unit * 16;
                LDSM_X4(bHf[2 * bt][0], bHf[2 * bt][1],
                        bHf[2 * bt + 1][0], bHf[2 * bt + 1][1], ad);
                LDSM_X4(bLf[2 * bt][0], bLf[2 * bt][1],
                        bLf[2 * bt + 1][0], bLf[2 * bt + 1][1],
                        ad + (OFF_BL - OFF_BH));
            }
            #pragma unroll
            for (int mt = 0; mt < 4; mt++) {
                uint32_t aH[4], aL[4];
                int row = wm + mt * 16 + lm_r + a_rowadd;
                int unit = kstep * 2 + a_uadd;
                uint32_t ad = st + OFF_AH + row * 80 + unit * 16;
                LDSM_X4(aH[0], aH[1], aH[2], aH[3], ad);
                LDSM_X4(aL[0], aL[1], aL[2], aL[3], ad + (OFF_AL - OFF_AH));
                #pragma unroll
                for (int nt = 0; nt < 4; nt++) {
                    HMMA(acc[mt][nt], aH, bHf[nt]);
                    HMMA(acc[mt][nt], aH, bLf[nt]);
                    HMMA(acc[mt][nt], aL, bHf[nt]);
                }
            }
        }
        __syncthreads();

        const int cn = c + NSTAGE;
        if (cn < NCHUNK) {
            const uint32_t sn = sb + (uint32_t)(cn & 1) * STAGE_BYTES;
            const size_t ka = (size_t)cn * BK;
            CP_ASYNC16(sn + OFF_AH + s_dst,      Ah + a_off + ka);
            CP_ASYNC16(sn + OFF_AH + s_dst + 16, Ah + a_off + ka + 8);
            CP_ASYNC16(sn + OFF_AL + s_dst,      Al + a_off + ka);
            CP_ASYNC16(sn + OFF_AL + s_dst + 16, Al + a_off + ka + 8);
            CP_ASYNC16(sn + OFF_BH + s_dst,      Bh + b_off + ka);
            CP_ASYNC16(sn + OFF_BH + s_dst + 16, Bh + b_off + ka + 8);
            CP_ASYNC16(sn + OFF_BL + s_dst,      Bl + b_off + ka);
            CP_ASYNC16(sn + OFF_BL + s_dst + 16, Bl + b_off + ka + 8);
            CP_COMMIT();
        }
    }

    // ---- epilogue: direct stores ----
    const int er = lane >> 2;
    const int ec = (lane & 3) * 2;
    #pragma unroll
    for (int mt = 0; mt < 4; mt++) {
        #pragma unroll
        for (int nt = 0; nt < 4; nt++) {
            int gn = bn + wn + nt * 8 + ec;
            if (gn >= PP) continue;
            int gm0 = bm + wm + mt * 16 + er;
            float* p0 = C + (size_t)gm0 * PP + gn;
            float* p1 = C + (size_t)(gm0 + 8) * PP + gn;
            p0[0] = acc[mt][nt][0];
            p1[0] = acc[mt][nt][2];
            if (gn + 1 < PP) {
                p0[1] = acc[mt][nt][1];
                p1[1] = acc[mt][nt][3];
            }
        }
    }
}

// ---------------- diag3 pass 1 on flattened (l, s) grid ---------------------
__global__ void pass1_kernel() {
    int idx = blockIdx.x * blockDim.x + threadIdx.x;
    if (idx >= TOT) return;
    int ls = idx % (LL * PP);
    int l = ls / PP, s = ls % PP;
    float v = g_cos[idx];
    if (l > 0    && s > 0)      v += g_cos[idx - PP - 1];
    if (l < 1023 && s < PP - 1) v += g_cos[idx + PP + 1];
    g_c1[idx] = v;
}

// ---------------- diag3 pass 2 (transposed spaces) + mask + scale -----------
__global__ void pass2_kernel(float* __restrict__ out) {
    int idx = blockIdx.x * blockDim.x + threadIdx.x;
    if (idx >= TOT) return;
    int b  = idx / (LL * PP);
    int ls = idx % (LL * PP);
    int l = ls / PP, s = ls % PP;
    int y = s / 63, x = s % 63;
    int lh = l >> 5, lw = l & 31;
    int lp = lw * 32 + lh;
    int sp = x * 63 + y;
    const float* c1 = g_c1 + (size_t)b * LL * PP;
    float v = 0.f;
    #pragma unroll
    for (int d = -1; d <= 1; d++) {
        int a = lp + d, tt = sp + d;
        if (a >= 0 && a < LL && tt >= 0 && tt < PP) {
            int l2 = ((a & 31) << 5) + (a >> 5);
            int s2 = (tt % 63) * 63 + (tt / 63);
            v += c1[(size_t)l2 * PP + s2];
        }
    }
    float mk = g_mmk[b * LL + l];
    float mp = g_mmp[b * PP + s];
    bool mm = ((mk > mp) && (mp > 0.5f)) || (mk == 1.0f);
    out[idx] = mm ? v * 10.0f : 0.0f;
}

// ---------------- softmax over l (stride PP) --------------------------------
__global__ void softmax_kernel(float* __restrict__ out) {
    int y = blockIdx.x;
    int b = blockIdx.y;
    int tx = threadIdx.x & 63;
    int tj = threadIdx.x >> 6;
    __shared__ float sm[4][64];
    __shared__ float ss[4][64];
    const size_t base = (size_t)b * LL * PP + (size_t)y * 63 + tx;
    float m = -1e30f, s = 0.f;
    if (tx < 63) {
        for (int l = tj; l < LL; l += 4) {
            float v = out[base + (size_t)l * PP];
            float nm = fmaxf(m, v);
            s = s * __expf(m - nm) + __expf(v - nm);
            m = nm;
        }
    }
    sm[tj][tx] = m; ss[tj][tx] = s;
    __syncthreads();
    if (tj == 0 && tx < 63) {
        float M = sm[0][tx], S = ss[0][tx];
        #pragma unroll
        for (int k = 1; k < 4; k++) {
            float m2 = sm[k][tx], s2 = ss[k][tx];
            float nm = fmaxf(M, m2);
            S = S * __expf(M - nm) + s2 * __expf(m2 - nm);
            M = nm;
        }
        sm[0][tx] = M; ss[0][tx] = 1.0f / S;
    }
    __syncthreads();
    if (tx < 63) {
        float M = sm[0][tx], R = ss[0][tx];
        for (int l = tj; l < LL; l += 4) {
            size_t o = base + (size_t)l * PP;
            out[o] = __expf(out[o] - M) * R;
        }
    }
}

// ---------------- launch ----------------------------------------------------
extern "C" void kernel_launch(void* const* d_in, const int* in_sizes, int n_in,
                              void* d_out, int out_size) {
    const float* f    = (const float*)d_in[0];
    const float* b    = (const float*)d_in[1];
    const float* mask = (const float*)d_in[2];
    float* out = (float*)d_out;

    cudaFuncSetAttribute(gemm_mma_kernel,
                         cudaFuncAttributeMaxDynamicSharedMemorySize, SMEM_GEMM_TOTAL);

    norm_kernel<<<BATCH * CH, 256>>>(b);
    buildK<<<(BATCH * LL * CH * 4 + 255) / 256, 256>>>(b);
    buildF<<<(BATCH * PPpad * CH * 4 + 255) / 256, 256>>>(f);
    mmk_kernel<<<(BATCH * LL + 255) / 256, 256>>>(mask);
    mmp_kernel<<<(BATCH * PP + 255) / 256, 256>>>(mask);

    gemm_mma_kernel<<<dim3(PPpad / 128, LL / 128, BATCH), 256, SMEM_GEMM_TOTAL>>>();

    int nb = (TOT + 255) / 256;
    pass1_kernel<<<nb, 256>>>();
    pass2_kernel<<<nb, 256>>>(out);
    softmax_kernel<<<dim3(63, BATCH), 256>>>(out);
}

// round 11
// speedup vs baseline: 1.9924x; 1.1337x over previous
#include <cuda_runtime.h>
#include <cuda_bf16.h>
#include <math.h>
#include <stdint.h>

#define BATCH 4
#define CH 64
#define LL 1024        // 32*32 kernel patches
#define PP 3969        // 63*63 f patches
#define PPpad 4096
#define KD 1024        // C * 4 * 4
#define BK 32          // K halves per chunk
#define NCHUNK (KD / BK)   // 32
#define NSTAGE 2

static const int TOT = BATCH * LL * PP;

// ---------------- scratch (static device arrays; no allocation) -------------
__device__ __nv_bfloat16 g_Kh[(size_t)BATCH * LL * KD];
__device__ __nv_bfloat16 g_Kl[(size_t)BATCH * LL * KD];
__device__ __nv_bfloat16 g_Fh[(size_t)BATCH * PPpad * KD];
__device__ __nv_bfloat16 g_Fl[(size_t)BATCH * PPpad * KD];
__device__ float g_cos[(size_t)BATCH * LL * PP];
__device__ float g_c1 [(size_t)BATCH * LL * PP];
__device__ float g_rnorm[BATCH * CH];
__device__ float g_mmk[BATCH * LL];
__device__ float g_mmp[BATCH * PP];

__device__ __forceinline__ int clamp64(int v) { return min(max(v, 0), 63); }

// ---------------- PTX helpers (baseline ISA only) ---------------------------
__device__ __forceinline__ uint32_t smem_u32(const void* p) {
    uint32_t a;
    asm("{ .reg .u64 t; cvta.to.shared.u64 t, %1; cvt.u32.u64 %0, t; }" : "=r"(a) : "l"(p));
    return a;
}
#define CP_ASYNC16(dst, src) \
    asm volatile("cp.async.cg.shared.global [%0], [%1], 16;" :: "r"(dst), "l"(src) : "memory")
#define CP_COMMIT() asm volatile("cp.async.commit_group;" ::: "memory")
#define CP_WAIT1()  asm volatile("cp.async.wait_group 1;" ::: "memory")
#define CP_WAIT0()  asm volatile("cp.async.wait_group 0;" ::: "memory")

#define LDSM_X4(r0, r1, r2, r3, addr) \
    asm volatile("ldmatrix.sync.aligned.m8n8.x4.shared.b16 {%0,%1,%2,%3}, [%4];" \
        : "=r"(r0), "=r"(r1), "=r"(r2), "=r"(r3) : "r"(addr))

#define HMMA(d, a, b) \
    asm volatile("mma.sync.aligned.m16n8k16.row.col.f32.bf16.bf16.f32 " \
        "{%0,%1,%2,%3}, {%4,%5,%6,%7}, {%8,%9}, {%0,%1,%2,%3};" \
        : "+f"((d)[0]), "+f"((d)[1]), "+f"((d)[2]), "+f"((d)[3]) \
        : "r"((a)[0]), "r"((a)[1]), "r"((a)[2]), "r"((a)[3]), \
          "r"((b)[0]), "r"((b)[1]))

__device__ __forceinline__ uint32_t pack_bf2(float a, float b) {
    __nv_bfloat162 t = __floats2bfloat162_rn(a, b);
    return *(uint32_t*)&t;
}

// fast exp on the FMA pipe (x <= 0 expected); ~2e-6 rel err
__device__ __forceinline__ float fexp(float x) {
    float t = fmaxf(x * 1.4426950408889634f, -126.0f);
    float fj = rintf(t);
    float f = t - fj;
    float p = 0.0013333558f;
    p = fmaf(p, f, 0.0096181291f);
    p = fmaf(p, f, 0.0555041087f);
    p = fmaf(p, f, 0.2402265069f);
    p = fmaf(p, f, 0.6931471806f);
    p = fmaf(p, f, 1.0f);
    int ji = (int)fj;
    float sc = __int_as_float((ji + 127) << 23);
    return p * sc;
}

// ---------------- per-(b,c) inverse L2 norm of b ----------------------------
__global__ void norm_kernel(const float* __restrict__ bin) {
    int bc = blockIdx.x;
    const float* ptr = bin + (size_t)bc * 4096;
    float s = 0.f;
    for (int i = threadIdx.x; i < 4096; i += 256) { float v = ptr[i]; s += v * v; }
    __shared__ float red[256];
    red[threadIdx.x] = s; __syncthreads();
    for (int st = 128; st > 0; st >>= 1) {
        if (threadIdx.x < st) red[threadIdx.x] += red[threadIdx.x + st];
        __syncthreads();
    }
    if (threadIdx.x == 0) g_rnorm[bc] = 1.0f / sqrtf(red[0] + 1e-8f);
}

// ---------------- build kernel matrix (bf16 hi/lo), k = c*16+i*4+j ----------
__global__ void buildK(const float* __restrict__ bin) {
    int idx = blockIdx.x * blockDim.x + threadIdx.x;
    if (idx >= BATCH * LL * CH * 4) return;
    int i = idx & 3;
    int c = (idx >> 2) & 63;
    int l = (idx >> 8) & 1023;
    int b = idx >> 18;
    int gy = l >> 5, gx = l & 31;
    int row = clamp64(gy * 2 + i - 1);
    float rn = g_rnorm[b * 64 + c];
    const float* src = bin + (((size_t)b * 64 + c) * 64 + row) * 64;
    int x0 = gx * 2 - 1;
    float v[4];
    v[0] = src[clamp64(x0 + 0)] * rn;
    v[1] = src[clamp64(x0 + 1)] * rn;
    v[2] = src[clamp64(x0 + 2)] * rn;
    v[3] = src[clamp64(x0 + 3)] * rn;
    float h[4], lo[4];
    #pragma unroll
    for (int j = 0; j < 4; j++) {
        h[j] = __bfloat162float(__float2bfloat16_rn(v[j]));
        lo[j] = v[j] - h[j];
    }
    uint2 hh = make_uint2(pack_bf2(h[0], h[1]), pack_bf2(h[2], h[3]));
    uint2 ll = make_uint2(pack_bf2(lo[0], lo[1]), pack_bf2(lo[2], lo[3]));
    *(uint2*)&g_Kh[(size_t)idx * 4] = hh;
    *(uint2*)&g_Kl[(size_t)idx * 4] = ll;
}

// ---------------- build f patch matrix (bf16 hi/lo), padded to 4096 rows ----
__global__ void buildF(const float* __restrict__ fin) {
    int idx = blockIdx.x * blockDim.x + threadIdx.x;
    if (idx >= BATCH * PPpad * CH * 4) return;
    int i = idx & 3;
    int c = (idx >> 2) & 63;
    int rem = idx >> 8;
    int p = rem & (PPpad - 1);
    int b = rem >> 12;
    if (p >= PP) p = PP - 1;           // duplicate pad rows (never stored to C)
    int y = p / 63, x = p % 63;
    int row = clamp64(y + i - 1);
    const float* src = fin + (((size_t)b * 64 + c) * 64 + row) * 64;
    int x0 = x - 1;
    float v[4];
    v[0] = src[clamp64(x0 + 0)];
    v[1] = src[clamp64(x0 + 1)];
    v[2] = src[clamp64(x0 + 2)];
    v[3] = src[clamp64(x0 + 3)];
    float h[4], lo[4];
    #pragma unroll
    for (int j = 0; j < 4; j++) {
        h[j] = __bfloat162float(__float2bfloat16_rn(v[j]));
        lo[j] = v[j] - h[j];
    }
    uint2 hh = make_uint2(pack_bf2(h[0], h[1]), pack_bf2(h[2], h[3]));
    uint2 ll = make_uint2(pack_bf2(lo[0], lo[1]), pack_bf2(lo[2], lo[3]));
    *(uint2*)&g_Fh[(size_t)idx * 4] = hh;
    *(uint2*)&g_Fl[(size_t)idx * 4] = ll;
}

// ---------------- mask patch means ------------------------------------------
__global__ void mmk_kernel(const float* __restrict__ mask) {
    int idx = blockIdx.x * blockDim.x + threadIdx.x;
    if (idx >= BATCH * LL) return;
    int b = idx >> 10, l = idx & 1023;
    int gy = l >> 5, gx = l & 31;
    const float* mp = mask + (size_t)b * 4096;
    float s = 0.f;
    #pragma unroll
    for (int i = 0; i < 4; i++) {
        int r = clamp64(gy * 2 + i - 1);
        #pragma unroll
        for (int j = 0; j < 4; j++)
            s += 1.0f - mp[r * 64 + clamp64(gx * 2 + j - 1)];
    }
    g_mmk[idx] = s * 0.0625f;
}

__global__ void mmp_kernel(const float* __restrict__ mask) {
    int idx = blockIdx.x * blockDim.x + threadIdx.x;
    if (idx >= BATCH * PP) return;
    int b = idx / PP, p = idx % PP;
    int y = p / 63, x = p % 63;
    const float* mp = mask + (size_t)b * 4096;
    float s = 0.f;
    #pragma unroll
    for (int i = 0; i < 4; i++) {
        int r = clamp64(y + i - 1);
        #pragma unroll
        for (int j = 0; j < 4; j++)
            s += 1.0f - mp[r * 64 + clamp64(x + j - 1)];
    }
    g_mmp[idx] = s * 0.0625f;
}

// ---------------- warp-MMA GEMM: cos = Km · F^T (bf16 3-split) --------------
#define OFF_AH 0
#define OFF_AL 10240
#define OFF_BH 20480
#define OFF_BL 30720
#define STAGE_BYTES 40960
#define SMEM_GEMM_TOTAL (NSTAGE * STAGE_BYTES)   // 81920

__global__ __launch_bounds__(256, 2) void gemm_mma_kernel() {
    extern __shared__ char smem[];
    const uint32_t sb = smem_u32(smem);
    const int tid = threadIdx.x;
    const int wid = tid >> 5;
    const int lane = tid & 31;

    const int bz = blockIdx.z;
    const int bm = blockIdx.y * 128;
    const int bn = blockIdx.x * 128;

    const __nv_bfloat16* Ah = g_Kh + (size_t)bz * LL * KD;
    const __nv_bfloat16* Al = g_Kl + (size_t)bz * LL * KD;
    const __nv_bfloat16* Bh = g_Fh + (size_t)bz * PPpad * KD;
    const __nv_bfloat16* Bl = g_Fl + (size_t)bz * PPpad * KD;
    float* C = g_cos + (size_t)bz * LL * PP;

    const int lrow = tid >> 1;
    const int lu0 = (tid & 1) * 2;
    const size_t a_off = (size_t)(bm + lrow) * KD + lu0 * 8;
    const size_t b_off = (size_t)(bn + lrow) * KD + lu0 * 8;
    const uint32_t s_dst = (uint32_t)(lrow * 80 + lu0 * 16);

    const int wm = (wid >> 2) * 64;
    const int wn = (wid & 3) * 32;

    const int lm_r = lane & 7;
    const int lm_mi = lane >> 3;
    const int a_rowadd = (lm_mi & 1) * 8;
    const int a_uadd = lm_mi >> 1;
    const int b_rowadd = (lm_mi >> 1) * 8;
    const int b_uadd = lm_mi & 1;

    float acc[4][4][4];
    #pragma unroll
    for (int i = 0; i < 4; i++)
        #pragma unroll
        for (int j = 0; j < 4; j++)
            #pragma unroll
            for (int q = 0; q < 4; q++) acc[i][j][q] = 0.f;

    #pragma unroll
    for (int c = 0; c < NSTAGE; c++) {
        const uint32_t st = sb + (uint32_t)c * STAGE_BYTES;
        const size_t ka = (size_t)c * BK;
        CP_ASYNC16(st + OFF_AH + s_dst,      Ah + a_off + ka);
        CP_ASYNC16(st + OFF_AH + s_dst + 16, Ah + a_off + ka + 8);
        CP_ASYNC16(st + OFF_AL + s_dst,      Al + a_off + ka);
        CP_ASYNC16(st + OFF_AL + s_dst + 16, Al + a_off + ka + 8);
        CP_ASYNC16(st + OFF_BH + s_dst,      Bh + b_off + ka);
        CP_ASYNC16(st + OFF_BH + s_dst + 16, Bh + b_off + ka + 8);
        CP_ASYNC16(st + OFF_BL + s_dst,      Bl + b_off + ka);
        CP_ASYNC16(st + OFF_BL + s_dst + 16, Bl + b_off + ka + 8);
        CP_COMMIT();
    }

    for (int c = 0; c < NCHUNK; c++) {
        if (c < NCHUNK - 1) { CP_WAIT1(); } else { CP_WAIT0(); }
        __syncthreads();
        const uint32_t st = sb + (uint32_t)(c & 1) * STAGE_BYTES;

        #pragma unroll
        for (int kstep = 0; kstep < 2; kstep++) {
            uint32_t bHf[4][2], bLf[4][2];
            #pragma unroll
            for (int bt = 0; bt < 2; bt++) {
                int row = wn + bt * 16 + lm_r + b_rowadd;
                int unit = kstep * 2 + b_uadd;
                uint32_t ad = st + OFF_BH + row * 80 + unit * 16;
                LDSM_X4(bHf[2 * bt][0], bHf[2 * bt][1],
                        bHf[2 * bt + 1][0], bHf[2 * bt + 1][1], ad);
                LDSM_X4(bLf[2 * bt][0], bLf[2 * bt][1],
                        bLf[2 * bt + 1][0], bLf[2 * bt + 1][1],
                        ad + (OFF_BL - OFF_BH));
            }
            #pragma unroll
            for (int mt = 0; mt < 4; mt++) {
                uint32_t aH[4], aL[4];
                int row = wm + mt * 16 + lm_r + a_rowadd;
                int unit = kstep * 2 + a_uadd;
                uint32_t ad = st + OFF_AH + row * 80 + unit * 16;
                LDSM_X4(aH[0], aH[1], aH[2], aH[3], ad);
                LDSM_X4(aL[0], aL[1], aL[2], aL[3], ad + (OFF_AL - OFF_AH));
                #pragma unroll
                for (int nt = 0; nt < 4; nt++) {
                    HMMA(acc[mt][nt], aH, bHf[nt]);
                    HMMA(acc[mt][nt], aH, bLf[nt]);
                    HMMA(acc[mt][nt], aL, bHf[nt]);
                }
            }
        }
        __syncthreads();

        const int cn = c + NSTAGE;
        if (cn < NCHUNK) {
            const uint32_t sn = sb + (uint32_t)(cn & 1) * STAGE_BYTES;
            const size_t ka = (size_t)cn * BK;
            CP_ASYNC16(sn + OFF_AH + s_dst,      Ah + a_off + ka);
            CP_ASYNC16(sn + OFF_AH + s_dst + 16, Ah + a_off + ka + 8);
            CP_ASYNC16(sn + OFF_AL + s_dst,      Al + a_off + ka);
            CP_ASYNC16(sn + OFF_AL + s_dst + 16, Al + a_off + ka + 8);
            CP_ASYNC16(sn + OFF_BH + s_dst,      Bh + b_off + ka);
            CP_ASYNC16(sn + OFF_BH + s_dst + 16, Bh + b_off + ka + 8);
            CP_ASYNC16(sn + OFF_BL + s_dst,      Bl + b_off + ka);
            CP_ASYNC16(sn + OFF_BL + s_dst + 16, Bl + b_off + ka + 8);
            CP_COMMIT();
        }
    }

    const int er = lane >> 2;
    const int ec = (lane & 3) * 2;
    #pragma unroll
    for (int mt = 0; mt < 4; mt++) {
        #pragma unroll
        for (int nt = 0; nt < 4; nt++) {
            int gn = bn + wn + nt * 8 + ec;
            if (gn >= PP) continue;
            int gm0 = bm + wm + mt * 16 + er;
            float* p0 = C + (size_t)gm0 * PP + gn;
            float* p1 = C + (size_t)(gm0 + 8) * PP + gn;
            p0[0] = acc[mt][nt][0];
            p1[0] = acc[mt][nt][2];
            if (gn + 1 < PP) {
                p0[1] = acc[mt][nt][1];
                p1[1] = acc[mt][nt][3];
            }
        }
    }
}

// ---------------- diag3 pass 1 on flattened (l, s) grid ---------------------
__global__ void pass1_kernel() {
    int idx = blockIdx.x * blockDim.x + threadIdx.x;
    if (idx >= TOT) return;
    int ls = idx % (LL * PP);
    int l = ls / PP, s = ls % PP;
    float v = g_cos[idx];
    if (l > 0    && s > 0)      v += g_cos[idx - PP - 1];
    if (l < 1023 && s < PP - 1) v += g_cos[idx + PP + 1];
    g_c1[idx] = v;
}

// ---------------- fused: diag3 pass 2 + mask + softmax over l ---------------
// Each block: 16 columns (s values) x all 1024 l, tile in smem (64KB).
// Threads: col = tid & 15, lgroup = tid >> 4 (16 groups); l = lg + 16*i.
#define FCOLS 16
#define SMEM_FUSE (LL * FCOLS * 4)    // 65536

__global__ __launch_bounds__(256, 3) void fuse_kernel(float* __restrict__ out) {
    extern __shared__ float sv[];      // [LL][FCOLS]
    __shared__ float redm[16][FCOLS];
    __shared__ float reds[16][FCOLS];
    __shared__ float colM[FCOLS];
    __shared__ float colR[FCOLS];

    const int tid = threadIdx.x;
    const int col = tid & 15;
    const int lg = tid >> 4;
    const int b = blockIdx.y;
    const int s = blockIdx.x * FCOLS + col;
    const bool active = (s < PP);

    const float* c1 = g_c1 + (size_t)b * LL * PP;
    float mp = 0.f;
    int y = 0, x = 0, sp = 0;
    if (active) {
        y = s / 63; x = s % 63;
        sp = x * 63 + y;
        mp = g_mmp[b * PP + s];
    }
    const bool ppp = (mp > 0.5f);

    float lmax = -1e30f;
    if (active) {
        #pragma unroll 4
        for (int i = 0; i < LL / 16; i++) {
            int l = lg + 16 * i;
            int lh = l >> 5, lw = l & 31;
            int lp = lw * 32 + lh;
            float v = 0.f;
            #pragma unroll
            for (int d = -1; d <= 1; d++) {
                int a = lp + d, tt = sp + d;
                if (a >= 0 && a < LL && tt >= 0 && tt < PP) {
                    int l2 = ((a & 31) << 5) + (a >> 5);
                    int s2 = (tt % 63) * 63 + (tt / 63);
                    v += c1[(size_t)l2 * PP + s2];
                }
            }
            float mk = g_mmk[b * LL + l];
            bool mm = ((mk > mp) && ppp) || (mk == 1.0f);
            float ov = mm ? v * 10.0f : 0.0f;
            sv[l * FCOLS + col] = ov;
            lmax = fmaxf(lmax, ov);
        }
    }
    redm[lg][col] = lmax;
    __syncthreads();
    if (lg == 0) {
        float M = redm[0][col];
        #pragma unroll
        for (int k = 1; k < 16; k++) M = fmaxf(M, redm[k][col]);
        colM[col] = M;
    }
    __syncthreads();

    float lsum = 0.f;
    if (active) {
        const float M = colM[col];
        #pragma unroll 4
        for (int i = 0; i < LL / 16; i++) {
            int l = lg + 16 * i;
            float e = fexp(sv[l * FCOLS + col] - M);
            sv[l * FCOLS + col] = e;
            lsum += e;
        }
    }
    reds[lg][col] = lsum;
    __syncthreads();
    if (lg == 0) {
        float S = reds[0][col];
        #pragma unroll
        for (int k = 1; k < 16; k++) S += reds[k][col];
        colR[col] = 1.0f / S;
    }
    __syncthreads();

    if (active) {
        const float R = colR[col];
        float* ob = out + (size_t)b * LL * PP + s;
        #pragma unroll 4
        for (int i = 0; i < LL / 16; i++) {
            int l = lg + 16 * i;
            ob[(size_t)l * PP] = sv[l * FCOLS + col] * R;
        }
    }
}

// ---------------- launch ----------------------------------------------------
extern "C" void kernel_launch(void* const* d_in, const int* in_sizes, int n_in,
                              void* d_out, int out_size) {
    const float* f    = (const float*)d_in[0];
    const float* b    = (const float*)d_in[1];
    const float* mask = (const float*)d_in[2];
    float* out = (float*)d_out;

    cudaFuncSetAttribute(gemm_mma_kernel,
                         cudaFuncAttributeMaxDynamicSharedMemorySize, SMEM_GEMM_TOTAL);
    cudaFuncSetAttribute(fuse_kernel,
                         cudaFuncAttributeMaxDynamicSharedMemorySize, SMEM_FUSE);

    norm_kernel<<<BATCH * CH, 256>>>(b);
    buildK<<<(BATCH * LL * CH * 4 + 255) / 256, 256>>>(b);
    buildF<<<(BATCH * PPpad * CH * 4 + 255) / 256, 256>>>(f);
    mmk_kernel<<<(BATCH * LL + 255) / 256, 256>>>(mask);
    mmp_kernel<<<(BATCH * PP + 255) / 256, 256>>>(mask);

    gemm_mma_kernel<<<dim3(PPpad / 128, LL / 128, BATCH), 256, SMEM_GEMM_TOTAL>>>();

    int nb = (TOT + 255) / 256;
    pass1_kernel<<<nb, 256>>>();
    fuse_kernel<<<dim3((PP + FCOLS - 1) / FCOLS, BATCH), 256, SMEM_FUSE>>>(out);
}